// round 6
// baseline (speedup 1.0000x reference)
#include <cuda_runtime.h>
#include <cuda_bf16.h>
#include <math.h>

// CoxPHLoss without sorting, fully fused single kernel:
//   S[t]  = sum_{j: time_j == t} exp(risk_j)         (4096 buckets)
//   L[t]  = log( sum_{t' >= t} S[t'] )               (suffix logsum)
//   nll   = sum_t d_t * L[t] - sum_{i: event_i} risk_i
//
// Per-block shared histogram packs (event_count << 44) | fixed_point_expsum
// into a single 64-bit shared atomic per element. Global combine uses integer
// atomics (deterministic). The last block to finish performs the 4096-bin
// suffix scan + NLL and resets all accumulators (self-cleaning for graph
// replays; device globals start zeroed on first use).

#define NBINS    4096
#define GRID1    296            // 148 SMs x 2 resident = one wave
#define THREADS1 1024
#define FIX_SHIFT 20
#define FIX_SCALE 1048576.0f            // 2^20
#define FIX_INV   9.5367431640625e-07   // 2^-20 exact
#define PACK_DSHIFT 44
#define PACK_SMASK ((1ull << PACK_DSHIFT) - 1ull)

// Scratch (device globals; zero-initialized at module load, self-cleaned after)
__device__ unsigned long long g_Sfix[NBINS];
__device__ int                g_D[NBINS];
__device__ double             g_partER[GRID1];
__device__ unsigned int       g_count;

__global__ __launch_bounds__(THREADS1, 2)
void cox_fused_kernel(const float* __restrict__ risk,
                      const int* __restrict__ time_,
                      const int* __restrict__ event_,
                      float* __restrict__ out,
                      int n)
{
    __shared__ unsigned long long s_P[NBINS];   // packed (D<<44)|Sfix
    __shared__ double s_red[32];
    __shared__ unsigned int s_ticket;

    const int tid = threadIdx.x;
    const int bid = blockIdx.x;
    const int lane = tid & 31, wid = tid >> 5;

    #pragma unroll
    for (int i = tid; i < NBINS; i += THREADS1)
        s_P[i] = 0ull;
    __syncthreads();

    double er = 0.0;   // sum of risk over events (this thread)

    const int nvec = n >> 2;
    const float4* r4 = reinterpret_cast<const float4*>(risk);
    const int4*   t4 = reinterpret_cast<const int4*>(time_);
    const int4*   e4 = reinterpret_cast<const int4*>(event_);

    const int gstride = GRID1 * THREADS1;
    const int gtid = bid * THREADS1 + tid;

    for (int i = gtid; i < nvec; i += gstride) {
        float4 r = r4[i];
        int4   t = t4[i];
        int4   e = e4[i];

        int t0 = t.x & (NBINS - 1);
        int t1 = t.y & (NBINS - 1);
        int t2 = t.z & (NBINS - 1);
        int t3 = t.w & (NBINS - 1);

        unsigned long long v0 = __float2ull_rn(__expf(r.x) * FIX_SCALE);
        unsigned long long v1 = __float2ull_rn(__expf(r.y) * FIX_SCALE);
        unsigned long long v2 = __float2ull_rn(__expf(r.z) * FIX_SCALE);
        unsigned long long v3 = __float2ull_rn(__expf(r.w) * FIX_SCALE);

        if (e.x) { v0 += (1ull << PACK_DSHIFT); er += (double)r.x; }
        if (e.y) { v1 += (1ull << PACK_DSHIFT); er += (double)r.y; }
        if (e.z) { v2 += (1ull << PACK_DSHIFT); er += (double)r.z; }
        if (e.w) { v3 += (1ull << PACK_DSHIFT); er += (double)r.w; }

        atomicAdd(&s_P[t0], v0);
        atomicAdd(&s_P[t1], v1);
        atomicAdd(&s_P[t2], v2);
        atomicAdd(&s_P[t3], v3);
    }

    // scalar tail (n not multiple of 4)
    for (int i = (nvec << 2) + gtid; i < n; i += gstride) {
        float r = risk[i];
        int   t = time_[i] & (NBINS - 1);
        unsigned long long v = __float2ull_rn(__expf(r) * FIX_SCALE);
        if (event_[i]) { v += (1ull << PACK_DSHIFT); er += (double)r; }
        atomicAdd(&s_P[t], v);
    }

    // block-reduce er -> g_partER[bid]
    #pragma unroll
    for (int off = 16; off > 0; off >>= 1)
        er += __shfl_down_sync(0xffffffffu, er, off);
    if (lane == 0) s_red[wid] = er;
    __syncthreads();
    if (wid == 0) {
        double v = s_red[lane];
        #pragma unroll
        for (int off = 16; off > 0; off >>= 1)
            v += __shfl_down_sync(0xffffffffu, v, off);
        if (lane == 0) g_partER[bid] = v;
    }

    // flush shared histogram -> global accumulators (integer atomics,
    // deterministic; unpack so global sums can't overflow the packing)
    __syncthreads();
    #pragma unroll
    for (int i = tid; i < NBINS; i += THREADS1) {
        unsigned long long v = s_P[i];
        if (v) {
            unsigned long long fx = v & PACK_SMASK;
            int d = (int)(v >> PACK_DSHIFT);
            atomicAdd(&g_Sfix[i], fx);
            if (d) atomicAdd(&g_D[i], d);
        }
    }

    // ---- last-block-done: final suffix scan + NLL + self-clean ----
    __threadfence();
    __syncthreads();
    if (tid == 0)
        s_ticket = atomicAdd(&g_count, 1u);
    __syncthreads();
    if (s_ticket != GRID1 - 1)
        return;

    // This is the last block; all other blocks' atomics are visible.
    {
        __shared__ double pref[NBINS];
        __shared__ double warpSums[32];
        __shared__ double redbuf[32];
        __shared__ long long dredbuf[32];

        const int base = tid * 4;   // 4 reversed-index elements per thread

        // local inclusive scan (reversed order: a[j] = S[4095-j])
        double v[4];
        int dloc[4];
        double run = 0.0;
        #pragma unroll
        for (int k = 0; k < 4; k++) {
            int t = NBINS - 1 - (base + k);
            run += (double)g_Sfix[t] * FIX_INV;
            v[k] = run;
            dloc[k] = g_D[t];
        }
        double total = run;

        // warp inclusive scan of per-thread totals
        double x = total;
        #pragma unroll
        for (int off = 1; off < 32; off <<= 1) {
            double y = __shfl_up_sync(0xffffffffu, x, off);
            if (lane >= off) x += y;
        }
        double wexcl = x - total;
        if (lane == 31) warpSums[wid] = x;
        __syncthreads();

        if (wid == 0) {
            double s = warpSums[lane];
            double xx = s;
            #pragma unroll
            for (int off = 1; off < 32; off <<= 1) {
                double y = __shfl_up_sync(0xffffffffu, xx, off);
                if (lane >= off) xx += y;
            }
            warpSums[lane] = xx - s;   // exclusive warp offsets
        }
        __syncthreads();

        double off0 = warpSums[wid] + wexcl;
        #pragma unroll
        for (int k = 0; k < 4; k++)
            pref[base + k] = off0 + v[k];
        __syncthreads();

        // contributions: d_t * log(suffix_sum[t]); suffix_sum[t]=pref[4095-t]
        double c = 0.0;
        long long dtot = 0;
        #pragma unroll
        for (int k = 0; k < 4; k++) {
            int j = base + k;
            int d = dloc[k];
            dtot += d;
            if (d > 0) c += (double)d * log(pref[j]);
        }
        // subtract event-risk sum (fixed-order across tid => deterministic)
        if (tid < GRID1) c -= g_partER[tid];

        #pragma unroll
        for (int off = 16; off > 0; off >>= 1) {
            c    += __shfl_down_sync(0xffffffffu, c, off);
            dtot += __shfl_down_sync(0xffffffffu, dtot, off);
        }
        if (lane == 0) { redbuf[wid] = c; dredbuf[wid] = dtot; }
        __syncthreads();
        if (wid == 0) {
            double cc = redbuf[lane];
            long long dd = dredbuf[lane];
            #pragma unroll
            for (int off = 16; off > 0; off >>= 1) {
                cc += __shfl_down_sync(0xffffffffu, cc, off);
                dd += __shfl_down_sync(0xffffffffu, dd, off);
            }
            if (lane == 0)
                out[0] = (dd > 0) ? (float)cc : 0.0f;
        }
        __syncthreads();

        // self-clean for the next replay
        #pragma unroll
        for (int i = tid; i < NBINS; i += THREADS1) {
            g_Sfix[i] = 0ull;
            g_D[i] = 0;
        }
        if (tid == 0)
            g_count = 0u;
    }
}

// ---------------------------------------------------------------------------
extern "C" void kernel_launch(void* const* d_in, const int* in_sizes, int n_in,
                              void* d_out, int out_size)
{
    const float* risk  = (const float*)d_in[0];
    const int*   time_ = (const int*)d_in[1];
    const int*   event_= (const int*)d_in[2];
    float* out = (float*)d_out;
    int n = in_sizes[0];

    cox_fused_kernel<<<GRID1, THREADS1>>>(risk, time_, event_, out, n);
}

// round 7
// speedup vs baseline: 2.1306x; 2.1306x over previous
#include <cuda_runtime.h>
#include <cuda_bf16.h>
#include <math.h>

// CoxPHLoss without sorting, fused single kernel:
//   S[t]  = sum_{j: time_j == t} exp(risk_j)         (4096 buckets)
//   L[t]  = log( sum_{t' >= t} S[t'] )               (suffix logsum)
//   nll   = sum_t d_t * L[t] - sum_{i: event_i} risk_i
//
// Hist uses 32-bit shared atomics (float S, int D) — measured fastest path.
// Global combine is fixed-point integer atomics (deterministic). Last block
// does the 4096-bin suffix scan + NLL and self-cleans the accumulators for
// the next graph replay.

#define NBINS    4096
#define GRID1    296            // 148 SMs x 2 resident = exactly one wave
#define THREADS1 1024
#define FIX_SCALE 1048576.0f            // 2^20
#define FIX_INV   9.5367431640625e-07   // 2^-20 exact

// Scratch (device globals; zero-initialized at load, self-cleaned per launch)
__device__ unsigned long long g_Sfix[NBINS];
__device__ int                g_D[NBINS];
__device__ double             g_partER[GRID1];
__device__ unsigned int       g_count;

union SmemU {
    struct {
        float S[NBINS];     // 16 KB
        int   D[NBINS];     // 16 KB
    } h;
    double pref[NBINS];     // 32 KB (final-phase alias)
};

__global__ __launch_bounds__(THREADS1, 2)
void cox_fused_kernel(const float* __restrict__ risk,
                      const int* __restrict__ time_,
                      const int* __restrict__ event_,
                      float* __restrict__ out,
                      int n)
{
    __shared__ SmemU u;
    __shared__ double s_red[32];
    __shared__ long long s_dred[32];
    __shared__ double warpSums[32];
    __shared__ unsigned int s_ticket;

    const int tid = threadIdx.x;
    const int bid = blockIdx.x;
    const int lane = tid & 31, wid = tid >> 5;

    #pragma unroll
    for (int i = tid; i < NBINS; i += THREADS1) {
        u.h.S[i] = 0.0f;
        u.h.D[i] = 0;
    }
    __syncthreads();

    double er = 0.0;   // sum of risk over events (this thread)

    const int nvec = n >> 2;
    const float4* r4 = reinterpret_cast<const float4*>(risk);
    const int4*   t4 = reinterpret_cast<const int4*>(time_);
    const int4*   e4 = reinterpret_cast<const int4*>(event_);

    const int gstride = GRID1 * THREADS1;
    const int gtid = bid * THREADS1 + tid;

    for (int i = gtid; i < nvec; i += gstride) {
        float4 r = r4[i];
        int4   t = t4[i];
        int4   e = e4[i];

        int t0 = t.x & (NBINS - 1);
        int t1 = t.y & (NBINS - 1);
        int t2 = t.z & (NBINS - 1);
        int t3 = t.w & (NBINS - 1);

        atomicAdd(&u.h.S[t0], __expf(r.x));
        atomicAdd(&u.h.S[t1], __expf(r.y));
        atomicAdd(&u.h.S[t2], __expf(r.z));
        atomicAdd(&u.h.S[t3], __expf(r.w));

        if (e.x) { atomicAdd(&u.h.D[t0], 1); er += (double)r.x; }
        if (e.y) { atomicAdd(&u.h.D[t1], 1); er += (double)r.y; }
        if (e.z) { atomicAdd(&u.h.D[t2], 1); er += (double)r.z; }
        if (e.w) { atomicAdd(&u.h.D[t3], 1); er += (double)r.w; }
    }

    // scalar tail (n not multiple of 4)
    for (int i = (nvec << 2) + gtid; i < n; i += gstride) {
        float r = risk[i];
        int   t = time_[i] & (NBINS - 1);
        atomicAdd(&u.h.S[t], __expf(r));
        if (event_[i]) { atomicAdd(&u.h.D[t], 1); er += (double)r; }
    }

    // block-reduce er -> g_partER[bid]
    #pragma unroll
    for (int off = 16; off > 0; off >>= 1)
        er += __shfl_down_sync(0xffffffffu, er, off);
    if (lane == 0) s_red[wid] = er;
    __syncthreads();
    if (wid == 0) {
        double v = s_red[lane];
        #pragma unroll
        for (int off = 16; off > 0; off >>= 1)
            v += __shfl_down_sync(0xffffffffu, v, off);
        if (lane == 0) g_partER[bid] = v;
    }
    __syncthreads();

    // flush shared histogram -> global fixed-point accumulators
    // (integer atomics => deterministic combine)
    #pragma unroll
    for (int i = tid; i < NBINS; i += THREADS1) {
        float s = u.h.S[i];
        int   d = u.h.D[i];
        if (s != 0.0f)
            atomicAdd(&g_Sfix[i], __float2ull_rn(s * FIX_SCALE));
        if (d != 0)
            atomicAdd(&g_D[i], d);
    }

    // ---- last-block-done: final suffix scan + NLL + self-clean ----
    __threadfence();
    __syncthreads();
    if (tid == 0)
        s_ticket = atomicAdd(&g_count, 1u);
    __syncthreads();
    if (s_ticket != GRID1 - 1)
        return;

    // Last block: all other blocks' atomics visible.
    const int base = tid * 4;   // 4 reversed-index elements per thread

    // local inclusive scan (reversed order: a[j] = S[4095-j])
    double v[4];
    int dloc[4];
    double run = 0.0;
    #pragma unroll
    for (int k = 0; k < 4; k++) {
        int t = NBINS - 1 - (base + k);
        run += (double)g_Sfix[t] * FIX_INV;
        v[k] = run;
        dloc[k] = g_D[t];
    }
    double total = run;

    // warp inclusive scan of per-thread totals
    double x = total;
    #pragma unroll
    for (int off = 1; off < 32; off <<= 1) {
        double y = __shfl_up_sync(0xffffffffu, x, off);
        if (lane >= off) x += y;
    }
    double wexcl = x - total;
    if (lane == 31) warpSums[wid] = x;
    __syncthreads();

    if (wid == 0) {
        double s = warpSums[lane];
        double xx = s;
        #pragma unroll
        for (int off = 1; off < 32; off <<= 1) {
            double y = __shfl_up_sync(0xffffffffu, xx, off);
            if (lane >= off) xx += y;
        }
        warpSums[lane] = xx - s;   // exclusive warp offsets
    }
    __syncthreads();   // also separates union reuse (hist -> pref)

    double off0 = warpSums[wid] + wexcl;
    #pragma unroll
    for (int k = 0; k < 4; k++)
        u.pref[base + k] = off0 + v[k];
    __syncthreads();

    // contributions: d_t * log(suffix_sum[t]); suffix_sum[t] = pref[4095-t]
    double c = 0.0;
    long long dtot = 0;
    #pragma unroll
    for (int k = 0; k < 4; k++) {
        int j = base + k;
        int d = dloc[k];
        dtot += d;
        if (d > 0) c += (double)d * log(u.pref[j]);
    }
    // subtract event-risk sum (fixed order across tid => deterministic)
    if (tid < GRID1) c -= g_partER[tid];

    #pragma unroll
    for (int off = 16; off > 0; off >>= 1) {
        c    += __shfl_down_sync(0xffffffffu, c, off);
        dtot += __shfl_down_sync(0xffffffffu, dtot, off);
    }
    if (lane == 0) { s_red[wid] = c; s_dred[wid] = dtot; }
    __syncthreads();
    if (wid == 0) {
        double cc = s_red[lane];
        long long dd = s_dred[lane];
        #pragma unroll
        for (int off = 16; off > 0; off >>= 1) {
            cc += __shfl_down_sync(0xffffffffu, cc, off);
            dd += __shfl_down_sync(0xffffffffu, dd, off);
        }
        if (lane == 0)
            out[0] = (dd > 0) ? (float)cc : 0.0f;
    }
    __syncthreads();

    // self-clean for next graph replay
    #pragma unroll
    for (int i = tid; i < NBINS; i += THREADS1) {
        g_Sfix[i] = 0ull;
        g_D[i] = 0;
    }
    if (tid == 0)
        g_count = 0u;
}

// ---------------------------------------------------------------------------
extern "C" void kernel_launch(void* const* d_in, const int* in_sizes, int n_in,
                              void* d_out, int out_size)
{
    const float* risk  = (const float*)d_in[0];
    const int*   time_ = (const int*)d_in[1];
    const int*   event_= (const int*)d_in[2];
    float* out = (float*)d_out;
    int n = in_sizes[0];

    cox_fused_kernel<<<GRID1, THREADS1>>>(risk, time_, event_, out, n);
}